// round 5
// baseline (speedup 1.0000x reference)
#include <cuda_runtime.h>
#include <math.h>

#define Bsz  256
#define Tlen 512
#define Dd   1024
#define Vv   32000
#define EPSV 1e-5f

#define BDIM 256
#define NBLK 128
#define NGRP 4          // 4 independent row-groups of 64 batch rows
#define MT   64
#define NT   32
#define KT   32
#define ASTR 66         // padded stride (floats) for transposed A tile

// ---------------- device scratch (no allocs allowed) ----------------
__device__ float g_u  [Bsz * Dd];   // u_t = z_{t-1} + emb[seq[:,t]]
__device__ float g_pre[Bsz * Dd];   // pre-LN activations
__device__ float g_z  [Bsz * Dd];   // final z
__device__ volatile unsigned g_arr[NBLK * 32];   // arrive flags, 128B apart
__device__ volatile unsigned g_rel[NGRP * 32];   // release word per group

// ---------------- packed fp32x2 helpers (Blackwell FFMA2 path) ----------------
__device__ __forceinline__ unsigned long long pk2(float x) {
    unsigned long long r;
    asm("mov.b64 %0, {%1, %1};" : "=l"(r) : "r"(__float_as_uint(x)));
    return r;
}
__device__ __forceinline__ unsigned long long ffma2(unsigned long long a,
                                                    unsigned long long b,
                                                    unsigned long long c) {
    unsigned long long d;
    asm("fma.rn.f32x2 %0, %1, %2, %3;" : "=l"(d) : "l"(a), "l"(b), "l"(c));
    return d;
}
__device__ __forceinline__ unsigned long long fadd2(unsigned long long a,
                                                    unsigned long long b) {
    unsigned long long d;
    asm("add.rn.f32x2 %0, %1, %2;" : "=l"(d) : "l"(a), "l"(b));
    return d;
}

// ---------------- group barrier: 32 blocks, distributed flags ----------------
// Release side: __threadfence before flag store. Acquire side: __threadfence
// after flag observation (before dependent cross-block loads).
__device__ __forceinline__ void group_barrier(int bid, unsigned phase) {
    __syncthreads();
    const int g = bid >> 5, l = bid & 31;
    if (l == 0) {
        unsigned t = threadIdx.x;
        if (t >= 1 && t < 32) {
            while (g_arr[((g << 5) + t) * 32] < phase) { }
        }
        if (t < 32) __threadfence();   // acquire for leader block
        __syncthreads();
        if (t == 0) { g_rel[g * 32] = phase; }
    } else {
        if (threadIdx.x == 0) {
            __threadfence();           // release own writes
            g_arr[bid * 32] = phase;
            while (g_rel[g * 32] < phase) { }
            __threadfence();           // acquire
        }
    }
    __syncthreads();
}

// ---------------- block reductions ----------------
__device__ __forceinline__ void blockReduce2(float& s, float& q, float* sm) {
    #pragma unroll
    for (int o = 16; o > 0; o >>= 1) {
        s += __shfl_xor_sync(0xffffffffu, s, o);
        q += __shfl_xor_sync(0xffffffffu, q, o);
    }
    int w = threadIdx.x >> 5;
    if ((threadIdx.x & 31) == 0) { sm[w] = s; sm[8 + w] = q; }
    __syncthreads();
    float ss = 0.f, qq = 0.f;
    #pragma unroll
    for (int i = 0; i < 8; i++) { ss += sm[i]; qq += sm[8 + i]; }
    __syncthreads();
    s = ss; q = qq;
}
__device__ __forceinline__ float blockMax(float v, float* sm) {
    #pragma unroll
    for (int o = 16; o > 0; o >>= 1) v = fmaxf(v, __shfl_xor_sync(0xffffffffu, v, o));
    int w = threadIdx.x >> 5;
    if ((threadIdx.x & 31) == 0) sm[w] = v;
    __syncthreads();
    float r = sm[0];
    #pragma unroll
    for (int i = 1; i < 8; i++) r = fmaxf(r, sm[i]);
    __syncthreads();
    return r;
}
__device__ __forceinline__ float blockSum(float v, float* sm) {
    #pragma unroll
    for (int o = 16; o > 0; o >>= 1) v += __shfl_xor_sync(0xffffffffu, v, o);
    int w = threadIdx.x >> 5;
    if ((threadIdx.x & 31) == 0) sm[w] = v;
    __syncthreads();
    float r = 0.f;
    #pragma unroll
    for (int i = 0; i < 8; i++) r += sm[i];
    __syncthreads();
    return r;
}

// ---------------- GEMM tile: C[64,32] += A[64,1024] * W[1024,32], FFMA2 ----------------
// Thread tile 2(m) x 4(n); tx = tid&7 (n/4), ty = tid>>3 (m/2).
// acc[i][p] = packed pair, i = m-row 0/1, p = n-pair (cols 4tx+2p, 4tx+2p+1).
template<int USECG>
__device__ __forceinline__ void gemm_tile(
    const float* __restrict__ A, const float* __restrict__ W, int ldw,
    int mBase, int nBase, float* As, float* Bs, unsigned long long (&acc)[2][2])
{
    const int tid = threadIdx.x;
    const int tx = tid & 7, ty = tid >> 3;
    acc[0][0] = 0ull; acc[0][1] = 0ull; acc[1][0] = 0ull; acc[1][1] = 0ull;

    const float* Ab = A + (size_t)mBase * Dd;
    const float* Wb = W + nBase;

    // chunk 0 -> buffer 0
    #pragma unroll
    for (int q = 0; q < 8; q++) {
        int i = tid + q * BDIM; int m = i >> 5, k = i & 31;
        const float* p = Ab + (size_t)m * Dd + k;
        As[k * ASTR + m] = USECG ? __ldcg(p) : __ldg(p);
    }
    #pragma unroll
    for (int q = 0; q < 4; q++) {
        int i = tid + q * BDIM; int kk = i >> 5, n = i & 31;
        Bs[kk * NT + n] = __ldg(Wb + (size_t)kk * ldw + n);
    }
    __syncthreads();

    const int nCh = Dd / KT;   // 32
    float ra[8], rb[4];
    for (int c = 0; c < nCh; c++) {
        const float* Asc = As + (c & 1) * (KT * ASTR);
        const float* Bsc = Bs + (c & 1) * (KT * NT);
        if (c + 1 < nCh) {
            int k0 = (c + 1) * KT;
            #pragma unroll
            for (int q = 0; q < 8; q++) {
                int i = tid + q * BDIM; int m = i >> 5, k = i & 31;
                const float* p = Ab + (size_t)m * Dd + k0 + k;
                ra[q] = USECG ? __ldcg(p) : __ldg(p);
            }
            #pragma unroll
            for (int q = 0; q < 4; q++) {
                int i = tid + q * BDIM; int kk = i >> 5, n = i & 31;
                rb[q] = __ldg(Wb + (size_t)(k0 + kk) * ldw + n);
            }
        }
        #pragma unroll
        for (int kk = 0; kk < KT; kk++) {
            float2 a2 = *(const float2*)(Asc + kk * ASTR + (ty << 1));
            ulonglong2 b2 = *(const ulonglong2*)(Bsc + kk * NT + (tx << 2));
            unsigned long long pax = pk2(a2.x), pay = pk2(a2.y);
            acc[0][0] = ffma2(pax, b2.x, acc[0][0]);
            acc[0][1] = ffma2(pax, b2.y, acc[0][1]);
            acc[1][0] = ffma2(pay, b2.x, acc[1][0]);
            acc[1][1] = ffma2(pay, b2.y, acc[1][1]);
        }
        if (c + 1 < nCh) {
            float* Asn = As + ((c + 1) & 1) * (KT * ASTR);
            float* Bsn = Bs + ((c + 1) & 1) * (KT * NT);
            #pragma unroll
            for (int q = 0; q < 8; q++) { int i = tid + q * BDIM; Asn[(i & 31) * ASTR + (i >> 5)] = ra[q]; }
            #pragma unroll
            for (int q = 0; q < 4; q++) { int i = tid + q * BDIM; Bsn[(i >> 5) * NT + (i & 31)] = rb[q]; }
        }
        __syncthreads();
    }
}

// ---------------- persistent kernel ----------------
__global__ void __launch_bounds__(BDIM, 1)
rnn_kernel(const float* __restrict__ hidden,
           const void*  __restrict__ seq,
           const float* __restrict__ emb,
           const float* __restrict__ Wdt,
           const float* __restrict__ bdt,
           const float* __restrict__ gamma,
           const float* __restrict__ beta,
           const float* __restrict__ Wv,
           const float* __restrict__ bv,
           float* __restrict__ outZ,
           float* __restrict__ outY)
{
    __shared__ __align__(16) float As[2 * KT * ASTR];
    __shared__ __align__(16) float Bs[2 * KT * NT];
    __shared__ float sred[16];
    const int tid = threadIdx.x;
    const int bid = blockIdx.x;
    const int tx = tid & 7, ty = tid >> 3;
    const int mB = (bid >> 5) * MT;        // group base rows
    const int nB = (bid & 31) * NT;        // column tile

    unsigned phase = g_rel[(bid >> 5) * 32];   // monotone across replays

    // ---- index-dtype sniff, per block, on a window safe under either dtype ----
    int bad = 0;
    {
        const int* s32 = (const int*)seq;
        int base = bid * 1024;                 // 128*1024 = 131072 words = min buffer size
        for (int i = tid; i < 1024; i += BDIM)
            if (((base + i) & 1) && __ldg(s32 + base + i) != 0) bad = 1;
    }
    bad = __syncthreads_or(bad);
    const int is64 = bad ? 0 : 1;              // int64 -> all odd words zero

    // ---- c = hidden @ W2 + b_dt, kept in registers for the whole run ----
    unsigned long long cacc[2][2];
    gemm_tile<0>(hidden, Wdt + Dd * Dd, Dd, mB, nB, As, Bs, cacc);
    {
        ulonglong2 bb = *(const ulonglong2*)(bdt + nB + (tx << 2));
        cacc[0][0] = fadd2(cacc[0][0], bb.x); cacc[0][1] = fadd2(cacc[0][1], bb.y);
        cacc[1][0] = fadd2(cacc[1][0], bb.x); cacc[1][1] = fadd2(cacc[1][1], bb.y);
    }

    // ---- u_0 = emb[seq[:,0]]  (z_0 = 0); block owns rows 2*bid, 2*bid+1 ----
    #pragma unroll
    for (int rr = 0; rr < 2; rr++) {
        int row = (bid << 1) + rr;
        int idx = is64 ? (int)__ldg(((const long long*)seq) + (size_t)row * Tlen)
                       :       __ldg(((const int*)seq)       + (size_t)row * Tlen);
        float4 e4 = __ldg(((const float4*)(emb + (size_t)idx * Dd)) + tid);
        __stcg(((float4*)(g_u + (size_t)row * Dd)) + tid, e4);
    }
    phase++; group_barrier(bid, phase);

    // ---- recurrence: 512 steps x (GEMM | LN), group-local barriers ----
    const float4 g4 = __ldg(((const float4*)gamma) + tid);
    const float4 b4 = __ldg(((const float4*)beta)  + tid);

    for (int t = 0; t < Tlen; t++) {
        {   // pre = u @ W1 + c + u
            unsigned long long acc[2][2];
            gemm_tile<1>(g_u, Wdt, Dd, mB, nB, As, Bs, acc);
            #pragma unroll
            for (int i = 0; i < 2; i++) {
                int m = mB + (ty << 1) + i;
                size_t off = (size_t)m * Dd + nB + (tx << 2);
                ulonglong2 uu = __ldcg((const ulonglong2*)(g_u + off));
                ulonglong2 po;
                po.x = fadd2(fadd2(acc[i][0], cacc[i][0]), uu.x);
                po.y = fadd2(fadd2(acc[i][1], cacc[i][1]), uu.y);
                __stcg((ulonglong2*)(g_pre + off), po);
            }
        }
        phase++; group_barrier(bid, phase);

        // LN + next-u prep; block owns full rows 2*bid, 2*bid+1
        #pragma unroll
        for (int rr = 0; rr < 2; rr++) {
            int row = (bid << 1) + rr;
            float4 v = __ldcg(((const float4*)(g_pre + (size_t)row * Dd)) + tid);
            float s = (v.x + v.y) + (v.z + v.w);
            float q = fmaf(v.x, v.x, fmaf(v.y, v.y, fmaf(v.z, v.z, v.w * v.w)));
            blockReduce2(s, q, sred);
            float mean = s * (1.f / Dd);
            float var  = q * (1.f / Dd) - mean * mean;
            float rstd = rsqrtf(var + EPSV);
            float4 z4;
            z4.x = fmaf((v.x - mean) * rstd, g4.x, b4.x);
            z4.y = fmaf((v.y - mean) * rstd, g4.y, b4.y);
            z4.z = fmaf((v.z - mean) * rstd, g4.z, b4.z);
            z4.w = fmaf((v.w - mean) * rstd, g4.w, b4.w);
            if (t + 1 < Tlen) {
                int idx = is64 ? (int)__ldg(((const long long*)seq) + (size_t)row * Tlen + t + 1)
                               :       __ldg(((const int*)seq)       + (size_t)row * Tlen + t + 1);
                float4 e4 = __ldg(((const float4*)(emb + (size_t)idx * Dd)) + tid);
                float4 u4 = make_float4(z4.x + e4.x, z4.y + e4.y, z4.z + e4.z, z4.w + e4.w);
                __stcg(((float4*)(g_u + (size_t)row * Dd)) + tid, u4);
            } else {
                __stcg(((float4*)(g_z + (size_t)row * Dd)) + tid, z4);
                if (outZ) __stcg(((float4*)(outZ + (size_t)row * Dd)) + tid, z4);
            }
        }
        phase++; group_barrier(bid, phase);
    }

    // ---- logits = z @ W_v + b_v : group-local, 1000 col tiles over 32 blocks ----
    {
        const int l = bid & 31;
        const int nColTiles = Vv / NT;   // 1000
        for (int tcol = l; tcol < nColTiles; tcol += 32) {
            int nB2 = tcol * NT;
            unsigned long long acc[2][2];
            gemm_tile<1>(g_z, Wv, Vv, mB, nB2, As, Bs, acc);
            ulonglong2 bb = *(const ulonglong2*)(bv + nB2 + (tx << 2));
            #pragma unroll
            for (int i = 0; i < 2; i++) {
                int m = mB + (ty << 1) + i;
                size_t off = (size_t)m * Vv + nB2 + (tx << 2);
                ulonglong2 oo;
                oo.x = fadd2(acc[i][0], bb.x);
                oo.y = fadd2(acc[i][1], bb.y);
                __stcg((ulonglong2*)(outY + off), oo);
            }
        }
    }
    phase++; group_barrier(bid, phase);

    // ---- log_softmax in place on outY, rows 2*bid, 2*bid+1 ----
    for (int rr = 0; rr < 2; rr++) {
        int row = (bid << 1) + rr;
        float* lrow = outY + (size_t)row * Vv;
        float m = -3.402823e38f;
        for (int i = tid; i < Vv; i += BDIM) m = fmaxf(m, __ldcg(lrow + i));
        m = blockMax(m, sred);
        float s = 0.f;
        for (int i = tid; i < Vv; i += BDIM) s += expf(__ldcg(lrow + i) - m);
        s = blockSum(s, sred);
        float ls = m + logf(s);
        for (int i = tid; i < Vv; i += BDIM) {
            float v = __ldcg(lrow + i);
            __stcg(lrow + i, v - ls);
        }
    }
}

// ---------------- launch ----------------
extern "C" void kernel_launch(void* const* d_in, const int* in_sizes, int n_in,
                              void* d_out, int out_size) {
    const float* hidden = (const float*)d_in[0];
    const void*  seq    = d_in[1];
    const float* emb    = (const float*)d_in[2];
    const float* Wdt    = (const float*)d_in[3];
    const float* bdt    = (const float*)d_in[4];
    const float* gamma  = (const float*)d_in[5];
    const float* beta   = (const float*)d_in[6];
    const float* Wv     = (const float*)d_in[7];
    const float* bv     = (const float*)d_in[8];
    float* out = (float*)d_out;

    float* outZ;
    float* outY;
    if (out_size >= Bsz * Dd + Bsz * Vv) { outZ = out; outY = out + Bsz * Dd; }
    else                                 { outZ = nullptr; outY = out; }

    rnn_kernel<<<NBLK, BDIM>>>(hidden, seq, emb, Wdt, bdt, gamma, beta, Wv, bv, outZ, outY);
}